// round 2
// baseline (speedup 1.0000x reference)
#include <cuda_runtime.h>
#include <math.h>

#define S_LEN    4096
#define BATCH    8
#define DMODEL   256
#define QPB      256
#define NTHREADS 256

__device__ __forceinline__ float ex2_fast(float x) {
    float r;
    asm("ex2.approx.ftz.f32 %0, %1;" : "=f"(r) : "f"(x));
    return r;
}

// out[b,s,:] = (sw/se) * Wv[:], where
//   se = sum_t 2^(l - m),  sw = sum_t 2^(l - m) * h_t
//   l(s,t) = aq*h_t - B2*|sz_s - sz_t|,   aq = (Wq.Wk/16)*log2e*h_s
//   m = |aq| * max_t|h_t|   (analytic upper bound; max pass eliminated)
__global__ __launch_bounds__(NTHREADS)
void dwsa_kernel(const float* __restrict__ x,
                 const float* __restrict__ Wq,
                 const float* __restrict__ Wk,
                 const float* __restrict__ Wv,
                 float* __restrict__ out)
{
    __shared__ float2 kp[S_LEN];   // (h, size-with-mask-sentinel) interleaved
    __shared__ float  sWv[DMODEL];
    __shared__ float  sW[QPB];
    __shared__ float  redDot[8];
    __shared__ float  redMax[8];

    const int tid  = threadIdx.x;
    const int b    = blockIdx.y;
    const int qblk = blockIdx.x;

    const float2* xb = (const float2*)(x + (size_t)b * S_LEN * 2);

    // ---- load keys, fold key mask into size sentinel, track max|h|
    float hm = 0.0f;
    #pragma unroll
    for (int t = tid; t < S_LEN; t += NTHREADS) {
        float2 kv = xb[t];                 // .x = size, .y = height
        float h = kv.y;
        kp[t] = make_float2(h, (h == 0.0f) ? 3.0e9f : kv.x);
        hm = fmaxf(hm, fabsf(h));
    }
    sWv[tid] = Wv[tid];

    // ---- block reductions: dot(Wq,Wk) and max|h|
    float p = Wq[tid] * Wk[tid];
    #pragma unroll
    for (int o = 16; o; o >>= 1) {
        p  += __shfl_down_sync(0xffffffffu, p, o);
        hm  = fmaxf(hm, __shfl_down_sync(0xffffffffu, hm, o));
    }
    if ((tid & 31) == 0) { redDot[tid >> 5] = p; redMax[tid >> 5] = hm; }
    __syncthreads();

    const float dotqk = redDot[0] + redDot[1] + redDot[2] + redDot[3]
                      + redDot[4] + redDot[5] + redDot[6] + redDot[7];
    const float hmax  = fmaxf(fmaxf(fmaxf(redMax[0], redMax[1]), fmaxf(redMax[2], redMax[3])),
                              fmaxf(fmaxf(redMax[4], redMax[5]), fmaxf(redMax[6], redMax[7])));

    const float LOG2E = 1.4426950408889634f;
    const float cs  = dotqk * (1.0f / 16.0f) * LOG2E;  // (Wq.Wk/sqrt(256)) in log2 domain
    const float nB2 = -0.5f * LOG2E;                   // -lambda in log2 domain

    // ---- this thread's query
    const float2 myx = xb[qblk * QPB + tid];
    const float hq = myx.y;
    const float zq = myx.x;
    const float aq = cs * hq;
    const float nm = -fabsf(aq) * hmax;                // -(upper bound of row max)

    // ---- single pass: sum e and sum e*h, 4 split accumulators, 8 keys/iter
    float s0 = 0.f, s1 = 0.f, s2 = 0.f, s3 = 0.f;
    float w0 = 0.f, w1 = 0.f, w2 = 0.f, w3 = 0.f;
    const float4* kp4 = (const float4*)kp;             // one float4 = 2 (h,sz) pairs

    #pragma unroll 2
    for (int t4 = 0; t4 < S_LEN / 2; t4 += 4) {
        float4 a = kp4[t4 + 0];
        float4 c = kp4[t4 + 1];
        float4 d = kp4[t4 + 2];
        float4 f = kp4[t4 + 3];

        float e0 = ex2_fast(fmaf(nB2, fabsf(zq - a.y), fmaf(aq, a.x, nm)));
        float e1 = ex2_fast(fmaf(nB2, fabsf(zq - a.w), fmaf(aq, a.z, nm)));
        float e2 = ex2_fast(fmaf(nB2, fabsf(zq - c.y), fmaf(aq, c.x, nm)));
        float e3 = ex2_fast(fmaf(nB2, fabsf(zq - c.w), fmaf(aq, c.z, nm)));
        float e4 = ex2_fast(fmaf(nB2, fabsf(zq - d.y), fmaf(aq, d.x, nm)));
        float e5 = ex2_fast(fmaf(nB2, fabsf(zq - d.w), fmaf(aq, d.z, nm)));
        float e6 = ex2_fast(fmaf(nB2, fabsf(zq - f.y), fmaf(aq, f.x, nm)));
        float e7 = ex2_fast(fmaf(nB2, fabsf(zq - f.w), fmaf(aq, f.z, nm)));

        s0 += e0; s1 += e1; s2 += e2; s3 += e3;
        s0 += e4; s1 += e5; s2 += e6; s3 += e7;
        w0 = fmaf(e0, a.x, w0); w1 = fmaf(e1, a.z, w1);
        w2 = fmaf(e2, c.x, w2); w3 = fmaf(e3, c.z, w3);
        w0 = fmaf(e4, d.x, w0); w1 = fmaf(e5, d.z, w1);
        w2 = fmaf(e6, f.x, w2); w3 = fmaf(e7, f.z, w3);
    }
    const float se = (s0 + s1) + (s2 + s3);
    const float sw = (w0 + w1) + (w2 + w3);
    sW[tid] = sw / se;
    __syncthreads();

    // ---- epilogue: out[row,:] = sW[row] * Wv[:], float4 coalesced
    float4* ob = (float4*)(out + ((size_t)b * S_LEN + (size_t)qblk * QPB) * DMODEL);
    const float4* wv4 = (const float4*)sWv;
    #pragma unroll 4
    for (int i = tid; i < QPB * (DMODEL / 4); i += NTHREADS) {
        const int row = i >> 6;            // DMODEL/4 = 64 float4 per row
        const float wv = sW[row];
        float4 v = wv4[i & 63];
        v.x *= wv; v.y *= wv; v.z *= wv; v.w *= wv;
        ob[i] = v;
    }
}

extern "C" void kernel_launch(void* const* d_in, const int* in_sizes, int n_in,
                              void* d_out, int out_size)
{
    const float* x  = (const float*)d_in[0];
    const float* Wq = (const float*)d_in[1];
    const float* Wk = (const float*)d_in[2];
    const float* Wv = (const float*)d_in[3];
    float* out = (float*)d_out;

    dim3 grid(S_LEN / QPB, BATCH);   // (16, 8) = 128 CTAs, one wave on 148 SMs
    dwsa_kernel<<<grid, NTHREADS>>>(x, Wq, Wk, Wv, out);
}